// round 10
// baseline (speedup 1.0000x reference)
#include <cuda_runtime.h>
#include <math.h>

#define NN 4096
#define DD 64
#define EE 32768
#define BB 32
#define NK 65    // intervals = 64 breakpoints + 1
#define WMAX 608 // max work items per layer (<= 512 + 65)

typedef unsigned long long ull;

// ------------------------- scratch (device globals) -------------------------
__device__ float  g_bufA[NN*DD];
__device__ float  g_bufB[NN*DD];
__device__ float  g_agg[NN*DD];
__device__ float  g_deg[NN];
__device__ float  g_P[3*NK*4096];
__device__ float  g_Q[3*NK*4096];
__device__ float  g_w[3*64], g_c[3*64];
__device__ int    g_rank[3*64];
__device__ int    g_ke[3*EE];
__device__ float4 g_edata[3*EE];
__device__ int    g_bhist[3*NK*128];
__device__ int    g_bbase[3*NK*128];
__device__ int    g_off[3*(NK+1)];
__device__ int2   g_work[3*WMAX];
__device__ int    g_nwork[4];
__device__ float  g_e[NN];
__device__ int    g_bstart[BB+1];

__device__ __forceinline__ float sigm(float x) { return 1.0f/(1.0f+expf(-x)); }

// packed f32x2 helpers
__device__ __forceinline__ ull pk2(float lo, float hi) {
    ull r;
    asm("mov.b64 %0, {%1, %2};" : "=l"(r) : "f"(lo), "f"(hi));
    return r;
}
__device__ __forceinline__ ull fma2(ull a, ull b, ull c) {
    ull d;
    asm("fma.rn.f32x2 %0, %1, %2, %3;" : "=l"(d) : "l"(a), "l"(b), "l"(c));
    return d;
}
__device__ __forceinline__ ull add2(ull a, ull b) {
    ull d;
    asm("add.rn.f32x2 %0, %1, %2;" : "=l"(d) : "l"(a), "l"(b));
    return d;
}
__device__ __forceinline__ void upk2(ull v, float& lo, float& hi) {
    asm("mov.b64 {%0, %1}, %2;" : "=f"(lo), "=f"(hi) : "l"(v));
}

// ------------------------- edge classification: all 3 layers + deg -------------------------
__global__ __launch_bounds__(256) void k_ke3(const float* __restrict__ W1,
                                             const float* __restrict__ b1,
                                             const float* __restrict__ ea,
                                             const int* __restrict__ eidx) {
    __shared__ float st[64];   // raw breakpoints
    __shared__ float ss[64];   // sorted breakpoints
    __shared__ int   hist[NK];
    int t = threadIdx.x, b = blockIdx.x;
    int e = b*256 + t;
    float a = ea[e];
    atomicAdd(&g_deg[eidx[EE + e]], 1.0f);
    for (int l = 0; l < 3; l++) {
        if (t < NK) hist[t] = 0;
        if (t < 64) {
            float w = W1[l*64 + t], c = b1[l*64 + t];
            float tt = (w != 0.0f) ? (-c / w) : __int_as_float(0x7f800000);
            st[t] = tt;
            if (b == 0) { g_w[l*64 + t] = w; g_c[l*64 + t] = c; }
        }
        __syncthreads();
        if (t < 64) {
            float tt = st[t];
            int r = 0;
            for (int j = 0; j < 64; j++)
                r += (st[j] < tt || (st[j] == tt && j < t)) ? 1 : 0;
            ss[r] = tt;
            if (b == 0) g_rank[l*64 + t] = r;
        }
        __syncthreads();
        int lo = 0, hi = 64;
        while (lo < hi) { int mid = (lo+hi)>>1; if (ss[mid] < a) lo = mid+1; else hi = mid; }
        g_ke[l*EE + e] = lo;
        atomicAdd(&hist[lo], 1);
        __syncthreads();
        if (t < NK) g_bhist[(l*NK + t)*128 + b] = hist[t];
        __syncthreads();
    }
}

// ------------------------- offsets + work list + bstart -------------------------
__global__ __launch_bounds__(256) void k_offsets(const int* __restrict__ bm) {
    __shared__ int stot[3*NK];
    int t = threadIdx.x, lane = t & 31, warp = t >> 5;
    for (int lk = warp; lk < 3*NK; lk += 8) {
        int4 v = ((const int4*)(g_bhist + lk*128))[lane];
        int p1 = v.x + v.y;
        int p2 = p1 + v.z;
        int tot = p2 + v.w;
        int inc = tot;
        #pragma unroll
        for (int off = 1; off < 32; off <<= 1) {
            int n = __shfl_up_sync(0xffffffffu, inc, off);
            if (lane >= off) inc += n;
        }
        int excl = inc - tot;
        int4 o;
        o.x = excl; o.y = excl + v.x; o.z = excl + p1; o.w = excl + p2;
        ((int4*)(g_bbase + lk*128))[lane] = o;
        if (lane == 31) stot[lk] = inc;
    }
    __syncthreads();
    if (t < 3) {
        int s = 0, w = 0;
        for (int k = 0; k < NK; k++) {
            g_off[t*(NK+1) + k] = s;
            int cnt = stot[t*NK + k];
            for (int c = 0; c < cnt; c += 64) {
                g_work[t*WMAX + w] = make_int2(k, s + c);
                w++;
            }
            s += cnt;
        }
        g_off[t*(NK+1) + NK] = s;
        g_nwork[t] = w;
    }
    if (t >= 128 && t <= 128 + BB) {
        int bb = t - 128;
        int lo = 0, hi = NN;
        while (lo < hi) { int mid = (lo+hi)>>1; if (bm[mid] < bb) lo = mid+1; else hi = mid; }
        g_bstart[bb] = lo;
    }
}

// ------------------------- scatter: deterministic, no global atomics -------------------------
__global__ __launch_bounds__(256) void k_scatter3(const float* __restrict__ ea,
                                                  const int* __restrict__ eidx) {
    __shared__ int sbase[NK];
    __shared__ int scnt[NK];
    int t = threadIdx.x, b = blockIdx.x;
    int e = b*256 + t;
    float a = ea[e];
    int s = eidx[e], d = eidx[EE + e];
    float4 rec;
    rec.x = __int_as_float(s);
    rec.y = __int_as_float(d);
    rec.z = a;
    rec.w = 0.0f;
    for (int l = 0; l < 3; l++) {
        if (t < NK) {
            sbase[t] = g_off[l*(NK+1) + t] + g_bbase[(l*NK + t)*128 + b];
            scnt[t] = 0;
        }
        __syncthreads();
        int k = g_ke[l*EE + e];
        int pos = sbase[k] + atomicAdd(&scnt[k], 1);
        g_edata[l*EE + pos] = rec;
        __syncthreads();
    }
}

// ------------------------- build P/Q tables (skip empty buckets) -------------------------
__global__ __launch_bounds__(256) void k_buildPQ3(const float* __restrict__ W2,
                                                  const float* __restrict__ b2) {
    __shared__ float sw[64], sc[64];
    __shared__ int srk[64];
    int l = blockIdx.z;
    int k = blockIdx.x;
    if (g_off[l*(NK+1) + k + 1] == g_off[l*(NK+1) + k]) return;  // empty bucket
    int t = threadIdx.x;
    if (t < 64) { sw[t] = g_w[l*64+t]; sc[t] = g_c[l*64+t]; srk[t] = g_rank[l*64+t]; }
    __syncthreads();
    int o0 = blockIdx.y*1024 + t;
    const float* W2l = W2 + l*64*4096;
    const float* b2l = b2 + l*4096;
    float p[4], q[4];
    #pragma unroll
    for (int j = 0; j < 4; j++) { p[j] = b2l[o0 + j*256]; q[j] = 0.0f; }
    for (int g = 0; g < 64; g++) {
        float w = sw[g], c = sc[g];
        bool act = (w > 0.0f) ? (srk[g] < k)
                 : ((w < 0.0f) ? (srk[g] >= k) : (c > 0.0f));
        if (!act) continue;
        const float* row = W2l + g*4096 + o0;
        #pragma unroll
        for (int j = 0; j < 4; j++) {
            float v = row[j*256];
            p[j] = fmaf(c, v, p[j]);
            q[j] = fmaf(w, v, q[j]);
        }
    }
    int base = (l*NK + k)*4096 + o0;
    #pragma unroll
    for (int j = 0; j < 4; j++) {
        g_P[base + j*256] = p[j];
        g_Q[base + j*256] = q[j];
    }
}

// ------------------------- fused 3-layer pre-MLP -------------------------
__global__ __launch_bounds__(256) void k_pre(const float* __restrict__ x,
                                             const float* __restrict__ W0, const float* __restrict__ b0,
                                             const float* __restrict__ W1, const float* __restrict__ b1,
                                             const float* __restrict__ W2, const float* __restrict__ b2,
                                             float* __restrict__ Y) {
    __shared__ float sW[8192];
    __shared__ float sA[2048];
    __shared__ float sT[1024];
    int t = threadIdx.x;
    int r0 = blockIdx.x * 16;
    for (int i = t; i < 2048; i += 256) sA[i] = x[r0*128 + i];
    for (int i = t; i < 8192; i += 256) sW[i] = W0[i];
    __syncthreads();
    int o = t & 63, mq = t >> 6;
    {
        float bv = b0[o];
        float a0 = bv, a1 = bv, a2 = bv, a3 = bv;
        #pragma unroll 4
        for (int i = 0; i < 128; i++) {
            float wv = sW[i*64 + o];
            a0 = fmaf(sA[(mq+ 0)*128 + i], wv, a0);
            a1 = fmaf(sA[(mq+ 4)*128 + i], wv, a1);
            a2 = fmaf(sA[(mq+ 8)*128 + i], wv, a2);
            a3 = fmaf(sA[(mq+12)*128 + i], wv, a3);
        }
        sT[(mq+ 0)*64+o] = fmaxf(a0, 0.0f);
        sT[(mq+ 4)*64+o] = fmaxf(a1, 0.0f);
        sT[(mq+ 8)*64+o] = fmaxf(a2, 0.0f);
        sT[(mq+12)*64+o] = fmaxf(a3, 0.0f);
    }
    __syncthreads();
    for (int i = t; i < 4096; i += 256) sW[i] = W1[i];
    __syncthreads();
    {
        float bv = b1[o];
        float a0 = bv, a1 = bv, a2 = bv, a3 = bv;
        #pragma unroll 4
        for (int i = 0; i < 64; i++) {
            float wv = sW[i*64 + o];
            a0 = fmaf(sT[(mq+ 0)*64 + i], wv, a0);
            a1 = fmaf(sT[(mq+ 4)*64 + i], wv, a1);
            a2 = fmaf(sT[(mq+ 8)*64 + i], wv, a2);
            a3 = fmaf(sT[(mq+12)*64 + i], wv, a3);
        }
        sA[(mq+ 0)*64+o] = fmaxf(a0, 0.0f);
        sA[(mq+ 4)*64+o] = fmaxf(a1, 0.0f);
        sA[(mq+ 8)*64+o] = fmaxf(a2, 0.0f);
        sA[(mq+12)*64+o] = fmaxf(a3, 0.0f);
    }
    __syncthreads();
    for (int i = t; i < 4096; i += 256) sW[i] = W2[i];
    __syncthreads();
    {
        float bv = b2[o];
        float a0 = bv, a1 = bv, a2 = bv, a3 = bv;
        #pragma unroll 4
        for (int i = 0; i < 64; i++) {
            float wv = sW[i*64 + o];
            a0 = fmaf(sA[(mq+ 0)*64 + i], wv, a0);
            a1 = fmaf(sA[(mq+ 4)*64 + i], wv, a1);
            a2 = fmaf(sA[(mq+ 8)*64 + i], wv, a2);
            a3 = fmaf(sA[(mq+12)*64 + i], wv, a3);
        }
        Y[(r0+mq+ 0)*64+o] = fmaxf(a0, 0.0f);
        Y[(r0+mq+ 4)*64+o] = fmaxf(a1, 0.0f);
        Y[(r0+mq+ 8)*64+o] = fmaxf(a2, 0.0f);
        Y[(r0+mq+12)*64+o] = fmaxf(a3, 0.0f);
    }
}

// ------------------------- message: work-list balanced, warp-per-edge -------------------------
__global__ __launch_bounds__(256) void k_msg(const float* __restrict__ X, int l) {
    __shared__ ull sP2[2048];        // paired: rows x 32 lanes, each ull = (out o, out o+32)
    __shared__ ull sQ2[2048];
    __shared__ ull sXd[8*64];        // per-warp x rows, duplicated (x,x)
    int nw = g_nwork[l];
    if (blockIdx.x >= nw) return;
    int2 wi = g_work[l*WMAX + blockIdx.x];
    int k = wi.x, start = wi.y;
    int bend = g_off[l*(NK+1) + k + 1];
    int t = threadIdx.x;
    const float* P = g_P + (l*NK + k)*4096;
    const float* Q = g_Q + (l*NK + k)*4096;
    float* fP = (float*)sP2;
    float* fQ = (float*)sQ2;
    for (int i = t; i < 4096; i += 256) {
        int row = i >> 6, col = i & 63;
        int o = col & 31, half = col >> 5;
        int di = (row*32 + o)*2 + half;
        fP[di] = P[i];
        fQ[di] = Q[i];
    }
    __syncthreads();
    int warp = t >> 5, lane = t & 31;
    const float2* X2 = (const float2*)X;
    ull* XD = sXd + warp*64;
    int myend = min(start + (warp+1)*8, bend);
    for (int idx = start + warp*8; idx < myend; idx++) {
        float4 rec = g_edata[l*EE + idx];
        int s  = __float_as_int(rec.x);
        int dn = __float_as_int(rec.y);
        float a = rec.z;
        float2 xv = X2[s*32 + lane];
        __syncwarp();
        XD[2*lane]     = pk2(xv.x, xv.x);
        XD[2*lane + 1] = pk2(xv.y, xv.y);
        __syncwarp();
        ull apack = pk2(a, a);
        ull acc0 = 0ull, acc1 = 0ull, acc2 = 0ull, acc3 = 0ull;
        #pragma unroll
        for (int i = 0; i < 64; i += 4) {
            ull m0 = fma2(apack, sQ2[(i+0)*32 + lane], sP2[(i+0)*32 + lane]);
            ull m1 = fma2(apack, sQ2[(i+1)*32 + lane], sP2[(i+1)*32 + lane]);
            ull m2 = fma2(apack, sQ2[(i+2)*32 + lane], sP2[(i+2)*32 + lane]);
            ull m3 = fma2(apack, sQ2[(i+3)*32 + lane], sP2[(i+3)*32 + lane]);
            acc0 = fma2(XD[i+0], m0, acc0);
            acc1 = fma2(XD[i+1], m1, acc1);
            acc2 = fma2(XD[i+2], m2, acc2);
            acc3 = fma2(XD[i+3], m3, acc3);
        }
        ull acc = add2(add2(acc0, acc1), add2(acc2, acc3));
        float r0, r1;
        upk2(acc, r0, r1);
        atomicAdd(&g_agg[dn*64 + lane],      r0);
        atomicAdd(&g_agg[dn*64 + lane + 32], r1);
    }
}

// ------------------------- fused conv + GRU (self-cleans g_agg) -------------------------
__global__ __launch_bounds__(256) void k_convgru(const float* __restrict__ X,
                                                 const float* __restrict__ rootW,
                                                 const float* __restrict__ cb,
                                                 const float* __restrict__ Wih,
                                                 const float* __restrict__ bih,
                                                 const float* __restrict__ Whh,
                                                 const float* __restrict__ bhh,
                                                 float* __restrict__ Y) {
    __shared__ float sH[1024];
    __shared__ float sConv[1024];
    __shared__ float sBig[6144];
    int t = threadIdx.x;
    int r0 = blockIdx.x * 16;
    for (int i = t; i < 1024; i += 256) sH[i] = X[r0*64 + i];
    for (int i = t; i < 4096; i += 256) sBig[i] = rootW[i];
    __syncthreads();
    int o = t & 63, mq = t >> 6;
    {
        float bv = cb[o];
        int n0 = r0 + mq;
        float a0 = fmaf(g_agg[(n0+ 0)*64+o], 1.0f/fmaxf(g_deg[n0+ 0], 1.0f), bv);
        float a1 = fmaf(g_agg[(n0+ 4)*64+o], 1.0f/fmaxf(g_deg[n0+ 4], 1.0f), bv);
        float a2 = fmaf(g_agg[(n0+ 8)*64+o], 1.0f/fmaxf(g_deg[n0+ 8], 1.0f), bv);
        float a3 = fmaf(g_agg[(n0+12)*64+o], 1.0f/fmaxf(g_deg[n0+12], 1.0f), bv);
        g_agg[(n0+ 0)*64+o] = 0.0f;
        g_agg[(n0+ 4)*64+o] = 0.0f;
        g_agg[(n0+ 8)*64+o] = 0.0f;
        g_agg[(n0+12)*64+o] = 0.0f;
        #pragma unroll 4
        for (int i = 0; i < 64; i++) {
            float wv = sBig[i*64 + o];
            a0 = fmaf(sH[(mq+ 0)*64 + i], wv, a0);
            a1 = fmaf(sH[(mq+ 4)*64 + i], wv, a1);
            a2 = fmaf(sH[(mq+ 8)*64 + i], wv, a2);
            a3 = fmaf(sH[(mq+12)*64 + i], wv, a3);
        }
        sConv[(mq+ 0)*64+o] = fmaxf(a0, 0.0f);
        sConv[(mq+ 4)*64+o] = fmaxf(a1, 0.0f);
        sConv[(mq+ 8)*64+o] = fmaxf(a2, 0.0f);
        sConv[(mq+12)*64+o] = fmaxf(a3, 0.0f);
    }
    __syncthreads();
    if (t < 192) {
        float gi[16], gh[16];
        float bi = bih[t], bh = bhh[t];
        #pragma unroll
        for (int m = 0; m < 16; m++) { gi[m] = bi; gh[m] = bh; }
        #pragma unroll 4
        for (int kk = 0; kk < 64; kk++) {
            float wi = Wih[kk*192 + t];
            float wh = Whh[kk*192 + t];
            #pragma unroll
            for (int m = 0; m < 16; m++) {
                gi[m] = fmaf(sConv[m*64 + kk], wi, gi[m]);
                gh[m] = fmaf(sH[m*64 + kk],    wh, gh[m]);
            }
        }
        #pragma unroll
        for (int m = 0; m < 16; m++) {
            sBig[m*192 + t]        = gi[m];
            sBig[3072 + m*192 + t] = gh[m];
        }
    }
    __syncthreads();
    #pragma unroll
    for (int j = 0; j < 4; j++) {
        int idx = t + j*256;
        int m = idx >> 6, d = idx & 63;
        float ir = sBig[m*192+d],      iz = sBig[m*192+64+d],      inn = sBig[m*192+128+d];
        float hr = sBig[3072+m*192+d], hz = sBig[3072+m*192+64+d], hn  = sBig[3072+m*192+128+d];
        float r = sigm(ir + hr);
        float z = sigm(iz + hz);
        float nv = tanhf(inn + r * hn);
        float h = sH[m*64 + d];
        Y[(r0+m)*64 + d] = (1.0f - z) * nv + z * h;
    }
}

// ------------------------- fused Set2Set (3 steps) + post-MLP + final -------------------------
__global__ __launch_bounds__(256) void k_s2s(const float* __restrict__ X,
                                             const float* __restrict__ Wih,
                                             const float* __restrict__ Whh,
                                             const float* __restrict__ bih,
                                             const float* __restrict__ bhh,
                                             const float* __restrict__ pW0, const float* __restrict__ pb0,
                                             const float* __restrict__ pW1, const float* __restrict__ pb1,
                                             const float* __restrict__ pW2, const float* __restrict__ pb2,
                                             const float* __restrict__ pW3, const float* __restrict__ pb3,
                                             float* __restrict__ out) {
    __shared__ float sqs[128];
    __shared__ float shh[64], scc[64];
    __shared__ float sg[256];
    __shared__ float sred[256];
    __shared__ float smax, sden;
    __shared__ float sy[64], sy2[64];
    int b = blockIdx.x;
    int t = threadIdx.x;
    int beg = g_bstart[b], end = g_bstart[b+1];
    if (t < 128) sqs[t] = 0.0f;
    if (t < 64) { shh[t] = 0.0f; scc[t] = 0.0f; }
    __syncthreads();
    for (int step = 0; step < 3; step++) {
        float acc0 = bih[t] + bhh[t], acc1 = 0.0f;
        #pragma unroll 8
        for (int i = 0; i < 128; i += 2) {
            acc0 = fmaf(sqs[i],   Wih[i*256 + t],     acc0);
            acc1 = fmaf(sqs[i+1], Wih[(i+1)*256 + t], acc1);
        }
        #pragma unroll 8
        for (int i = 0; i < 64; i += 2) {
            acc0 = fmaf(shh[i],   Whh[i*256 + t],     acc0);
            acc1 = fmaf(shh[i+1], Whh[(i+1)*256 + t], acc1);
        }
        sg[t] = acc0 + acc1;
        __syncthreads();
        if (t < 64) {
            float c = sigm(sg[64+t]) * scc[t] + sigm(sg[t]) * tanhf(sg[128+t]);
            float h = sigm(sg[192+t]) * tanhf(c);
            scc[t] = c; shh[t] = h;
        }
        __syncthreads();
        int warp = t >> 5, lane = t & 31;
        float mloc = -3.4e38f;
        for (int n = beg + warp; n < end; n += 8) {
            float v = X[n*64 + lane]*shh[lane] + X[n*64 + 32 + lane]*shh[32 + lane];
            #pragma unroll
            for (int off = 16; off; off >>= 1) v += __shfl_down_sync(0xffffffffu, v, off);
            v = __shfl_sync(0xffffffffu, v, 0);
            if (lane == 0) g_e[n] = v;
            mloc = fmaxf(mloc, v);
        }
        if (lane == 0) sred[warp] = mloc;
        __syncthreads();
        if (t == 0) {
            float m = sred[0];
            for (int j = 1; j < 8; j++) m = fmaxf(m, sred[j]);
            smax = m;
        }
        __syncthreads();
        float m = smax;
        float dl = 0.0f;
        for (int n = beg + t; n < end; n += 256) dl += expf(g_e[n] - m);
        sred[t] = dl;
        __syncthreads();
        if (t < 128) sred[t] += sred[t+128];
        __syncthreads();
        if (t < 64) sred[t] += sred[t+64];
        __syncthreads();
        if (t == 0) { float s = 0.0f; for (int j = 0; j < 64; j++) s += sred[j]; sden = s; }
        __syncthreads();
        float den = sden;
        int d = t & 63, quarter = t >> 6;
        float ra = 0.0f;
        for (int n = beg + quarter; n < end; n += 4) ra += expf(g_e[n] - m) * X[n*64 + d];
        __syncthreads();
        sred[t] = ra;
        __syncthreads();
        if (t < 64) {
            sqs[64 + t] = (sred[t] + sred[t+64] + sred[t+128] + sred[t+192]) / den;
            sqs[t]      = shh[t];
        }
        __syncthreads();
    }
    if (t < 64) {
        float acc = pb0[t];
        #pragma unroll 8
        for (int i = 0; i < 128; i++) acc = fmaf(sqs[i], pW0[i*64 + t], acc);
        sy[t] = fmaxf(acc, 0.0f);
    }
    __syncthreads();
    if (t < 64) {
        float acc = pb1[t];
        #pragma unroll 8
        for (int i = 0; i < 64; i++) acc = fmaf(sy[i], pW1[i*64 + t], acc);
        sy2[t] = fmaxf(acc, 0.0f);
    }
    __syncthreads();
    if (t < 64) {
        float acc = pb2[t];
        #pragma unroll 8
        for (int i = 0; i < 64; i++) acc = fmaf(sy2[i], pW2[i*64 + t], acc);
        sy[t] = fmaxf(acc, 0.0f);
    }
    __syncthreads();
    if (t < 32) {
        float v = sy[t]*pW3[t] + sy[t+32]*pW3[t+32];
        #pragma unroll
        for (int off = 16; off; off >>= 1) v += __shfl_down_sync(0xffffffffu, v, off);
        if (t == 0) out[b] = v + pb3[0];
    }
}

// ------------------------- host -------------------------
extern "C" void kernel_launch(void* const* d_in, const int* in_sizes, int n_in,
                              void* d_out, int out_size) {
    const float* x         = (const float*)d_in[0];
    const float* edge_attr = (const float*)d_in[1];
    const int*   edge_idx  = (const int*)  d_in[2];
    const int*   batch_map = (const int*)  d_in[3];
    const float* pre_W0 = (const float*)d_in[4];
    const float* pre_b0 = (const float*)d_in[5];
    const float* pre_W1 = (const float*)d_in[6];
    const float* pre_b1 = (const float*)d_in[7];
    const float* pre_W2 = (const float*)d_in[8];
    const float* pre_b2 = (const float*)d_in[9];
    const float* enn_W1 = (const float*)d_in[10];
    const float* enn_b1 = (const float*)d_in[11];
    const float* enn_W2 = (const float*)d_in[12];
    const float* enn_b2 = (const float*)d_in[13];
    const float* root_W = (const float*)d_in[14];
    const float* conv_b = (const float*)d_in[15];
    const float* gru_Wih = (const float*)d_in[16];
    const float* gru_Whh = (const float*)d_in[17];
    const float* gru_bih = (const float*)d_in[18];
    const float* gru_bhh = (const float*)d_in[19];
    const float* s2s_Wih = (const float*)d_in[20];
    const float* s2s_Whh = (const float*)d_in[21];
    const float* s2s_bih = (const float*)d_in[22];
    const float* s2s_bhh = (const float*)d_in[23];
    const float* post_W0 = (const float*)d_in[24];
    const float* post_b0 = (const float*)d_in[25];
    const float* post_W1 = (const float*)d_in[26];
    const float* post_b1 = (const float*)d_in[27];
    const float* post_W2 = (const float*)d_in[28];
    const float* post_b2 = (const float*)d_in[29];
    const float* post_W3 = (const float*)d_in[30];
    const float* post_b3 = (const float*)d_in[31];

    float *bufA, *bufB, *agg, *deg;
    cudaGetSymbolAddress((void**)&bufA, g_bufA);
    cudaGetSymbolAddress((void**)&bufB, g_bufB);
    cudaGetSymbolAddress((void**)&agg,  g_agg);
    cudaGetSymbolAddress((void**)&deg,  g_deg);

    cudaMemsetAsync(deg, 0, NN*sizeof(float));
    cudaMemsetAsync(agg, 0, NN*DD*sizeof(float));

    k_ke3<<<128, 256>>>(enn_W1, enn_b1, edge_attr, edge_idx);
    k_offsets<<<1, 256>>>(batch_map);
    k_buildPQ3<<<dim3(65, 4, 3), 256>>>(enn_W2, enn_b2);
    k_scatter3<<<128, 256>>>(edge_attr, edge_idx);

    k_pre<<<NN/16, 256>>>(x, pre_W0, pre_b0, pre_W1, pre_b1, pre_W2, pre_b2, bufA);

    float* curbuf = bufA;
    float* nxtbuf = bufB;
    for (int l = 0; l < 3; l++) {
        k_msg<<<WMAX, 256>>>(curbuf, l);
        k_convgru<<<NN/16, 256>>>(curbuf, root_W + l*4096, conv_b + l*64,
                                  gru_Wih + l*64*192, gru_bih + l*192,
                                  gru_Whh + l*64*192, gru_bhh + l*192, nxtbuf);
        float* sw = curbuf; curbuf = nxtbuf; nxtbuf = sw;
    }

    k_s2s<<<BB, 256>>>(curbuf, s2s_Wih, s2s_Whh, s2s_bih, s2s_bhh,
                       post_W0, post_b0, post_W1, post_b1,
                       post_W2, post_b2, post_W3, post_b3, (float*)d_out);
}

// round 11
// speedup vs baseline: 1.0081x; 1.0081x over previous
#include <cuda_runtime.h>
#include <math.h>

#define NN 4096
#define DD 64
#define EE 32768
#define BB 32
#define NK 65    // intervals = 64 breakpoints + 1
#define WMAX 608 // max work items per layer (<= 512 + 65)

typedef unsigned long long ull;

// ------------------------- scratch (device globals) -------------------------
__device__ float  g_bufA[NN*DD];
__device__ float  g_bufB[NN*DD];
__device__ float  g_agg[NN*DD];
__device__ float  g_deg[NN];
__device__ float  g_P[3*NK*4096];
__device__ float  g_Q[3*NK*4096];
__device__ float  g_w[3*64], g_c[3*64];
__device__ int    g_rank[3*64];
__device__ int    g_ke[3*EE];
__device__ float4 g_edata[3*EE];
__device__ int    g_bhist[3*NK*128];
__device__ int    g_bbase[3*NK*128];
__device__ int    g_off[3*(NK+1)];
__device__ int2   g_work[3*WMAX];
__device__ int    g_nwork[4];
__device__ float  g_e[NN];
__device__ int    g_bstart[BB+1];

__device__ __forceinline__ float sigm(float x) { return 1.0f/(1.0f+expf(-x)); }

// packed f32x2 helpers
__device__ __forceinline__ ull pk2(float lo, float hi) {
    ull r;
    asm("mov.b64 %0, {%1, %2};" : "=l"(r) : "f"(lo), "f"(hi));
    return r;
}
__device__ __forceinline__ ull fma2(ull a, ull b, ull c) {
    ull d;
    asm("fma.rn.f32x2 %0, %1, %2, %3;" : "=l"(d) : "l"(a), "l"(b), "l"(c));
    return d;
}
__device__ __forceinline__ ull add2(ull a, ull b) {
    ull d;
    asm("add.rn.f32x2 %0, %1, %2;" : "=l"(d) : "l"(a), "l"(b));
    return d;
}
__device__ __forceinline__ void upk2(ull v, float& lo, float& hi) {
    asm("mov.b64 {%0, %1}, %2;" : "=f"(lo), "=f"(hi) : "l"(v));
}

// ------------------------- edge classification: all 3 layers + deg -------------------------
__global__ __launch_bounds__(256) void k_ke3(const float* __restrict__ W1,
                                             const float* __restrict__ b1,
                                             const float* __restrict__ ea,
                                             const int* __restrict__ eidx) {
    __shared__ float st[64];   // raw breakpoints
    __shared__ float ss[64];   // sorted breakpoints
    __shared__ int   hist[NK];
    int t = threadIdx.x, b = blockIdx.x;
    int e = b*256 + t;
    float a = ea[e];
    atomicAdd(&g_deg[eidx[EE + e]], 1.0f);
    for (int l = 0; l < 3; l++) {
        if (t < NK) hist[t] = 0;
        if (t < 64) {
            float w = W1[l*64 + t], c = b1[l*64 + t];
            float tt = (w != 0.0f) ? (-c / w) : __int_as_float(0x7f800000);
            st[t] = tt;
            if (b == 0) { g_w[l*64 + t] = w; g_c[l*64 + t] = c; }
        }
        __syncthreads();
        if (t < 64) {
            float tt = st[t];
            int r = 0;
            for (int j = 0; j < 64; j++)
                r += (st[j] < tt || (st[j] == tt && j < t)) ? 1 : 0;
            ss[r] = tt;
            if (b == 0) g_rank[l*64 + t] = r;
        }
        __syncthreads();
        int lo = 0, hi = 64;
        while (lo < hi) { int mid = (lo+hi)>>1; if (ss[mid] < a) lo = mid+1; else hi = mid; }
        g_ke[l*EE + e] = lo;
        atomicAdd(&hist[lo], 1);
        __syncthreads();
        if (t < NK) g_bhist[(l*NK + t)*128 + b] = hist[t];
        __syncthreads();
    }
}

// ------------------------- offsets + work list + bstart -------------------------
__global__ __launch_bounds__(256) void k_offsets(const int* __restrict__ bm) {
    __shared__ int stot[3*NK];
    int t = threadIdx.x, lane = t & 31, warp = t >> 5;
    for (int lk = warp; lk < 3*NK; lk += 8) {
        int4 v = ((const int4*)(g_bhist + lk*128))[lane];
        int p1 = v.x + v.y;
        int p2 = p1 + v.z;
        int tot = p2 + v.w;
        int inc = tot;
        #pragma unroll
        for (int off = 1; off < 32; off <<= 1) {
            int n = __shfl_up_sync(0xffffffffu, inc, off);
            if (lane >= off) inc += n;
        }
        int excl = inc - tot;
        int4 o;
        o.x = excl; o.y = excl + v.x; o.z = excl + p1; o.w = excl + p2;
        ((int4*)(g_bbase + lk*128))[lane] = o;
        if (lane == 31) stot[lk] = inc;
    }
    __syncthreads();
    if (t < 3) {
        int s = 0, w = 0;
        for (int k = 0; k < NK; k++) {
            g_off[t*(NK+1) + k] = s;
            int cnt = stot[t*NK + k];
            for (int c = 0; c < cnt; c += 64) {
                g_work[t*WMAX + w] = make_int2(k, s + c);
                w++;
            }
            s += cnt;
        }
        g_off[t*(NK+1) + NK] = s;
        g_nwork[t] = w;
    }
    if (t >= 128 && t <= 128 + BB) {
        int bb = t - 128;
        int lo = 0, hi = NN;
        while (lo < hi) { int mid = (lo+hi)>>1; if (bm[mid] < bb) lo = mid+1; else hi = mid; }
        g_bstart[bb] = lo;
    }
}

// ------------------------- scatter: deterministic, no global atomics -------------------------
__global__ __launch_bounds__(256) void k_scatter3(const float* __restrict__ ea,
                                                  const int* __restrict__ eidx) {
    __shared__ int sbase[NK];
    __shared__ int scnt[NK];
    int t = threadIdx.x, b = blockIdx.x;
    int e = b*256 + t;
    float a = ea[e];
    int s = eidx[e], d = eidx[EE + e];
    float4 rec;
    rec.x = __int_as_float(s);
    rec.y = __int_as_float(d);
    rec.z = a;
    rec.w = 0.0f;
    for (int l = 0; l < 3; l++) {
        if (t < NK) {
            sbase[t] = g_off[l*(NK+1) + t] + g_bbase[(l*NK + t)*128 + b];
            scnt[t] = 0;
        }
        __syncthreads();
        int k = g_ke[l*EE + e];
        int pos = sbase[k] + atomicAdd(&scnt[k], 1);
        g_edata[l*EE + pos] = rec;
        __syncthreads();
    }
}

// ------------------------- build P/Q tables (skip empty buckets) -------------------------
__global__ __launch_bounds__(256) void k_buildPQ3(const float* __restrict__ W2,
                                                  const float* __restrict__ b2) {
    __shared__ float sw[64], sc[64];
    __shared__ int srk[64];
    int l = blockIdx.z;
    int k = blockIdx.x;
    if (g_off[l*(NK+1) + k + 1] == g_off[l*(NK+1) + k]) return;  // empty bucket
    int t = threadIdx.x;
    if (t < 64) { sw[t] = g_w[l*64+t]; sc[t] = g_c[l*64+t]; srk[t] = g_rank[l*64+t]; }
    __syncthreads();
    int o0 = blockIdx.y*1024 + t;
    const float* W2l = W2 + l*64*4096;
    const float* b2l = b2 + l*4096;
    float p[4], q[4];
    #pragma unroll
    for (int j = 0; j < 4; j++) { p[j] = b2l[o0 + j*256]; q[j] = 0.0f; }
    for (int g = 0; g < 64; g++) {
        float w = sw[g], c = sc[g];
        bool act = (w > 0.0f) ? (srk[g] < k)
                 : ((w < 0.0f) ? (srk[g] >= k) : (c > 0.0f));
        if (!act) continue;
        const float* row = W2l + g*4096 + o0;
        #pragma unroll
        for (int j = 0; j < 4; j++) {
            float v = row[j*256];
            p[j] = fmaf(c, v, p[j]);
            q[j] = fmaf(w, v, q[j]);
        }
    }
    int base = (l*NK + k)*4096 + o0;
    #pragma unroll
    for (int j = 0; j < 4; j++) {
        g_P[base + j*256] = p[j];
        g_Q[base + j*256] = q[j];
    }
}

// ------------------------- fused 3-layer pre-MLP -------------------------
__global__ __launch_bounds__(256) void k_pre(const float* __restrict__ x,
                                             const float* __restrict__ W0, const float* __restrict__ b0,
                                             const float* __restrict__ W1, const float* __restrict__ b1,
                                             const float* __restrict__ W2, const float* __restrict__ b2,
                                             float* __restrict__ Y) {
    __shared__ float sW[8192];
    __shared__ float sA[2048];
    __shared__ float sT[1024];
    int t = threadIdx.x;
    int r0 = blockIdx.x * 16;
    for (int i = t; i < 2048; i += 256) sA[i] = x[r0*128 + i];
    for (int i = t; i < 8192; i += 256) sW[i] = W0[i];
    __syncthreads();
    int o = t & 63, mq = t >> 6;
    {
        float bv = b0[o];
        float a0 = bv, a1 = bv, a2 = bv, a3 = bv;
        #pragma unroll 4
        for (int i = 0; i < 128; i++) {
            float wv = sW[i*64 + o];
            a0 = fmaf(sA[(mq+ 0)*128 + i], wv, a0);
            a1 = fmaf(sA[(mq+ 4)*128 + i], wv, a1);
            a2 = fmaf(sA[(mq+ 8)*128 + i], wv, a2);
            a3 = fmaf(sA[(mq+12)*128 + i], wv, a3);
        }
        sT[(mq+ 0)*64+o] = fmaxf(a0, 0.0f);
        sT[(mq+ 4)*64+o] = fmaxf(a1, 0.0f);
        sT[(mq+ 8)*64+o] = fmaxf(a2, 0.0f);
        sT[(mq+12)*64+o] = fmaxf(a3, 0.0f);
    }
    __syncthreads();
    for (int i = t; i < 4096; i += 256) sW[i] = W1[i];
    __syncthreads();
    {
        float bv = b1[o];
        float a0 = bv, a1 = bv, a2 = bv, a3 = bv;
        #pragma unroll 4
        for (int i = 0; i < 64; i++) {
            float wv = sW[i*64 + o];
            a0 = fmaf(sT[(mq+ 0)*64 + i], wv, a0);
            a1 = fmaf(sT[(mq+ 4)*64 + i], wv, a1);
            a2 = fmaf(sT[(mq+ 8)*64 + i], wv, a2);
            a3 = fmaf(sT[(mq+12)*64 + i], wv, a3);
        }
        sA[(mq+ 0)*64+o] = fmaxf(a0, 0.0f);
        sA[(mq+ 4)*64+o] = fmaxf(a1, 0.0f);
        sA[(mq+ 8)*64+o] = fmaxf(a2, 0.0f);
        sA[(mq+12)*64+o] = fmaxf(a3, 0.0f);
    }
    __syncthreads();
    for (int i = t; i < 4096; i += 256) sW[i] = W2[i];
    __syncthreads();
    {
        float bv = b2[o];
        float a0 = bv, a1 = bv, a2 = bv, a3 = bv;
        #pragma unroll 4
        for (int i = 0; i < 64; i++) {
            float wv = sW[i*64 + o];
            a0 = fmaf(sA[(mq+ 0)*64 + i], wv, a0);
            a1 = fmaf(sA[(mq+ 4)*64 + i], wv, a1);
            a2 = fmaf(sA[(mq+ 8)*64 + i], wv, a2);
            a3 = fmaf(sA[(mq+12)*64 + i], wv, a3);
        }
        Y[(r0+mq+ 0)*64+o] = fmaxf(a0, 0.0f);
        Y[(r0+mq+ 4)*64+o] = fmaxf(a1, 0.0f);
        Y[(r0+mq+ 8)*64+o] = fmaxf(a2, 0.0f);
        Y[(r0+mq+12)*64+o] = fmaxf(a3, 0.0f);
    }
}

// ------------------------- message: work-list balanced, warp-per-edge -------------------------
__global__ __launch_bounds__(256) void k_msg(const float* __restrict__ X, int l) {
    __shared__ ull sP2[2048];        // paired: rows x 32 lanes, each ull = (out o, out o+32)
    __shared__ ull sQ2[2048];
    __shared__ ull sXd[8*64];        // per-warp x rows, duplicated (x,x)
    int nw = g_nwork[l];
    if (blockIdx.x >= nw) return;
    int2 wi = g_work[l*WMAX + blockIdx.x];
    int k = wi.x, start = wi.y;
    int bend = g_off[l*(NK+1) + k + 1];
    int t = threadIdx.x;
    const float* P = g_P + (l*NK + k)*4096;
    const float* Q = g_Q + (l*NK + k)*4096;
    float* fP = (float*)sP2;
    float* fQ = (float*)sQ2;
    for (int i = t; i < 4096; i += 256) {
        int row = i >> 6, col = i & 63;
        int o = col & 31, half = col >> 5;
        int di = (row*32 + o)*2 + half;
        fP[di] = P[i];
        fQ[di] = Q[i];
    }
    __syncthreads();
    int warp = t >> 5, lane = t & 31;
    const float2* X2 = (const float2*)X;
    ull* XD = sXd + warp*64;
    int myend = min(start + (warp+1)*8, bend);
    for (int idx = start + warp*8; idx < myend; idx++) {
        float4 rec = g_edata[l*EE + idx];
        int s  = __float_as_int(rec.x);
        int dn = __float_as_int(rec.y);
        float a = rec.z;
        float2 xv = X2[s*32 + lane];
        __syncwarp();
        XD[2*lane]     = pk2(xv.x, xv.x);
        XD[2*lane + 1] = pk2(xv.y, xv.y);
        __syncwarp();
        ull apack = pk2(a, a);
        ull acc0 = 0ull, acc1 = 0ull, acc2 = 0ull, acc3 = 0ull;
        #pragma unroll
        for (int i = 0; i < 64; i += 4) {
            ull m0 = fma2(apack, sQ2[(i+0)*32 + lane], sP2[(i+0)*32 + lane]);
            ull m1 = fma2(apack, sQ2[(i+1)*32 + lane], sP2[(i+1)*32 + lane]);
            ull m2 = fma2(apack, sQ2[(i+2)*32 + lane], sP2[(i+2)*32 + lane]);
            ull m3 = fma2(apack, sQ2[(i+3)*32 + lane], sP2[(i+3)*32 + lane]);
            acc0 = fma2(XD[i+0], m0, acc0);
            acc1 = fma2(XD[i+1], m1, acc1);
            acc2 = fma2(XD[i+2], m2, acc2);
            acc3 = fma2(XD[i+3], m3, acc3);
        }
        ull acc = add2(add2(acc0, acc1), add2(acc2, acc3));
        float r0, r1;
        upk2(acc, r0, r1);
        atomicAdd(&g_agg[dn*64 + lane],      r0);
        atomicAdd(&g_agg[dn*64 + lane + 32], r1);
    }
}

// ------------------------- fused conv + GRU (self-cleans g_agg) -------------------------
__global__ __launch_bounds__(256) void k_convgru(const float* __restrict__ X,
                                                 const float* __restrict__ rootW,
                                                 const float* __restrict__ cb,
                                                 const float* __restrict__ Wih,
                                                 const float* __restrict__ bih,
                                                 const float* __restrict__ Whh,
                                                 const float* __restrict__ bhh,
                                                 float* __restrict__ Y) {
    __shared__ float sH[1024];
    __shared__ float sConv[1024];
    __shared__ float sBig[6144];
    int t = threadIdx.x;
    int r0 = blockIdx.x * 16;
    for (int i = t; i < 1024; i += 256) sH[i] = X[r0*64 + i];
    for (int i = t; i < 4096; i += 256) sBig[i] = rootW[i];
    __syncthreads();
    int o = t & 63, mq = t >> 6;
    {
        float bv = cb[o];
        int n0 = r0 + mq;
        float a0 = fmaf(g_agg[(n0+ 0)*64+o], 1.0f/fmaxf(g_deg[n0+ 0], 1.0f), bv);
        float a1 = fmaf(g_agg[(n0+ 4)*64+o], 1.0f/fmaxf(g_deg[n0+ 4], 1.0f), bv);
        float a2 = fmaf(g_agg[(n0+ 8)*64+o], 1.0f/fmaxf(g_deg[n0+ 8], 1.0f), bv);
        float a3 = fmaf(g_agg[(n0+12)*64+o], 1.0f/fmaxf(g_deg[n0+12], 1.0f), bv);
        g_agg[(n0+ 0)*64+o] = 0.0f;
        g_agg[(n0+ 4)*64+o] = 0.0f;
        g_agg[(n0+ 8)*64+o] = 0.0f;
        g_agg[(n0+12)*64+o] = 0.0f;
        #pragma unroll 4
        for (int i = 0; i < 64; i++) {
            float wv = sBig[i*64 + o];
            a0 = fmaf(sH[(mq+ 0)*64 + i], wv, a0);
            a1 = fmaf(sH[(mq+ 4)*64 + i], wv, a1);
            a2 = fmaf(sH[(mq+ 8)*64 + i], wv, a2);
            a3 = fmaf(sH[(mq+12)*64 + i], wv, a3);
        }
        sConv[(mq+ 0)*64+o] = fmaxf(a0, 0.0f);
        sConv[(mq+ 4)*64+o] = fmaxf(a1, 0.0f);
        sConv[(mq+ 8)*64+o] = fmaxf(a2, 0.0f);
        sConv[(mq+12)*64+o] = fmaxf(a3, 0.0f);
    }
    __syncthreads();
    if (t < 192) {
        float gi[16], gh[16];
        float bi = bih[t], bh = bhh[t];
        #pragma unroll
        for (int m = 0; m < 16; m++) { gi[m] = bi; gh[m] = bh; }
        #pragma unroll 4
        for (int kk = 0; kk < 64; kk++) {
            float wi = Wih[kk*192 + t];
            float wh = Whh[kk*192 + t];
            #pragma unroll
            for (int m = 0; m < 16; m++) {
                gi[m] = fmaf(sConv[m*64 + kk], wi, gi[m]);
                gh[m] = fmaf(sH[m*64 + kk],    wh, gh[m]);
            }
        }
        #pragma unroll
        for (int m = 0; m < 16; m++) {
            sBig[m*192 + t]        = gi[m];
            sBig[3072 + m*192 + t] = gh[m];
        }
    }
    __syncthreads();
    #pragma unroll
    for (int j = 0; j < 4; j++) {
        int idx = t + j*256;
        int m = idx >> 6, d = idx & 63;
        float ir = sBig[m*192+d],      iz = sBig[m*192+64+d],      inn = sBig[m*192+128+d];
        float hr = sBig[3072+m*192+d], hz = sBig[3072+m*192+64+d], hn  = sBig[3072+m*192+128+d];
        float r = sigm(ir + hr);
        float z = sigm(iz + hz);
        float nv = tanhf(inn + r * hn);
        float h = sH[m*64 + d];
        Y[(r0+m)*64 + d] = (1.0f - z) * nv + z * h;
    }
}

// ------------------------- fused Set2Set (3 steps) + post-MLP + final -------------------------
__global__ __launch_bounds__(256) void k_s2s(const float* __restrict__ X,
                                             const float* __restrict__ Wih,
                                             const float* __restrict__ Whh,
                                             const float* __restrict__ bih,
                                             const float* __restrict__ bhh,
                                             const float* __restrict__ pW0, const float* __restrict__ pb0,
                                             const float* __restrict__ pW1, const float* __restrict__ pb1,
                                             const float* __restrict__ pW2, const float* __restrict__ pb2,
                                             const float* __restrict__ pW3, const float* __restrict__ pb3,
                                             float* __restrict__ out) {
    __shared__ float sqs[128];
    __shared__ float shh[64], scc[64];
    __shared__ float sg[256];
    __shared__ float sred[256];
    __shared__ float smax, sden;
    __shared__ float sy[64], sy2[64];
    int b = blockIdx.x;
    int t = threadIdx.x;
    int beg = g_bstart[b], end = g_bstart[b+1];
    if (t < 128) sqs[t] = 0.0f;
    if (t < 64) { shh[t] = 0.0f; scc[t] = 0.0f; }
    __syncthreads();
    for (int step = 0; step < 3; step++) {
        float acc0 = bih[t] + bhh[t], acc1 = 0.0f;
        #pragma unroll 8
        for (int i = 0; i < 128; i += 2) {
            acc0 = fmaf(sqs[i],   Wih[i*256 + t],     acc0);
            acc1 = fmaf(sqs[i+1], Wih[(i+1)*256 + t], acc1);
        }
        #pragma unroll 8
        for (int i = 0; i < 64; i += 2) {
            acc0 = fmaf(shh[i],   Whh[i*256 + t],     acc0);
            acc1 = fmaf(shh[i+1], Whh[(i+1)*256 + t], acc1);
        }
        sg[t] = acc0 + acc1;
        __syncthreads();
        if (t < 64) {
            float c = sigm(sg[64+t]) * scc[t] + sigm(sg[t]) * tanhf(sg[128+t]);
            float h = sigm(sg[192+t]) * tanhf(c);
            scc[t] = c; shh[t] = h;
        }
        __syncthreads();
        int warp = t >> 5, lane = t & 31;
        float mloc = -3.4e38f;
        for (int n = beg + warp; n < end; n += 8) {
            float v = X[n*64 + lane]*shh[lane] + X[n*64 + 32 + lane]*shh[32 + lane];
            #pragma unroll
            for (int off = 16; off; off >>= 1) v += __shfl_down_sync(0xffffffffu, v, off);
            v = __shfl_sync(0xffffffffu, v, 0);
            if (lane == 0) g_e[n] = v;
            mloc = fmaxf(mloc, v);
        }
        if (lane == 0) sred[warp] = mloc;
        __syncthreads();
        if (t == 0) {
            float m = sred[0];
            for (int j = 1; j < 8; j++) m = fmaxf(m, sred[j]);
            smax = m;
        }
        __syncthreads();
        float m = smax;
        float dl = 0.0f;
        for (int n = beg + t; n < end; n += 256) dl += expf(g_e[n] - m);
        sred[t] = dl;
        __syncthreads();
        if (t < 128) sred[t] += sred[t+128];
        __syncthreads();
        if (t < 64) sred[t] += sred[t+64];
        __syncthreads();
        if (t == 0) { float s = 0.0f; for (int j = 0; j < 64; j++) s += sred[j]; sden = s; }
        __syncthreads();
        float den = sden;
        int d = t & 63, quarter = t >> 6;
        float ra = 0.0f;
        for (int n = beg + quarter; n < end; n += 4) ra += expf(g_e[n] - m) * X[n*64 + d];
        __syncthreads();
        sred[t] = ra;
        __syncthreads();
        if (t < 64) {
            sqs[64 + t] = (sred[t] + sred[t+64] + sred[t+128] + sred[t+192]) / den;
            sqs[t]      = shh[t];
        }
        __syncthreads();
    }
    if (t < 64) {
        float acc = pb0[t];
        #pragma unroll 8
        for (int i = 0; i < 128; i++) acc = fmaf(sqs[i], pW0[i*64 + t], acc);
        sy[t] = fmaxf(acc, 0.0f);
    }
    __syncthreads();
    if (t < 64) {
        float acc = pb1[t];
        #pragma unroll 8
        for (int i = 0; i < 64; i++) acc = fmaf(sy[i], pW1[i*64 + t], acc);
        sy2[t] = fmaxf(acc, 0.0f);
    }
    __syncthreads();
    if (t < 64) {
        float acc = pb2[t];
        #pragma unroll 8
        for (int i = 0; i < 64; i++) acc = fmaf(sy2[i], pW2[i*64 + t], acc);
        sy[t] = fmaxf(acc, 0.0f);
    }
    __syncthreads();
    if (t < 32) {
        float v = sy[t]*pW3[t] + sy[t+32]*pW3[t+32];
        #pragma unroll
        for (int off = 16; off; off >>= 1) v += __shfl_down_sync(0xffffffffu, v, off);
        if (t == 0) out[b] = v + pb3[0];
    }
}

// ------------------------- host -------------------------
extern "C" void kernel_launch(void* const* d_in, const int* in_sizes, int n_in,
                              void* d_out, int out_size) {
    const float* x         = (const float*)d_in[0];
    const float* edge_attr = (const float*)d_in[1];
    const int*   edge_idx  = (const int*)  d_in[2];
    const int*   batch_map = (const int*)  d_in[3];
    const float* pre_W0 = (const float*)d_in[4];
    const float* pre_b0 = (const float*)d_in[5];
    const float* pre_W1 = (const float*)d_in[6];
    const float* pre_b1 = (const float*)d_in[7];
    const float* pre_W2 = (const float*)d_in[8];
    const float* pre_b2 = (const float*)d_in[9];
    const float* enn_W1 = (const float*)d_in[10];
    const float* enn_b1 = (const float*)d_in[11];
    const float* enn_W2 = (const float*)d_in[12];
    const float* enn_b2 = (const float*)d_in[13];
    const float* root_W = (const float*)d_in[14];
    const float* conv_b = (const float*)d_in[15];
    const float* gru_Wih = (const float*)d_in[16];
    const float* gru_Whh = (const float*)d_in[17];
    const float* gru_bih = (const float*)d_in[18];
    const float* gru_bhh = (const float*)d_in[19];
    const float* s2s_Wih = (const float*)d_in[20];
    const float* s2s_Whh = (const float*)d_in[21];
    const float* s2s_bih = (const float*)d_in[22];
    const float* s2s_bhh = (const float*)d_in[23];
    const float* post_W0 = (const float*)d_in[24];
    const float* post_b0 = (const float*)d_in[25];
    const float* post_W1 = (const float*)d_in[26];
    const float* post_b1 = (const float*)d_in[27];
    const float* post_W2 = (const float*)d_in[28];
    const float* post_b2 = (const float*)d_in[29];
    const float* post_W3 = (const float*)d_in[30];
    const float* post_b3 = (const float*)d_in[31];

    float *bufA, *bufB, *agg, *deg;
    cudaGetSymbolAddress((void**)&bufA, g_bufA);
    cudaGetSymbolAddress((void**)&bufB, g_bufB);
    cudaGetSymbolAddress((void**)&agg,  g_agg);
    cudaGetSymbolAddress((void**)&deg,  g_deg);

    cudaMemsetAsync(deg, 0, NN*sizeof(float));
    cudaMemsetAsync(agg, 0, NN*DD*sizeof(float));

    k_ke3<<<128, 256>>>(enn_W1, enn_b1, edge_attr, edge_idx);
    k_offsets<<<1, 256>>>(batch_map);
    k_buildPQ3<<<dim3(65, 4, 3), 256>>>(enn_W2, enn_b2);
    k_scatter3<<<128, 256>>>(edge_attr, edge_idx);

    k_pre<<<NN/16, 256>>>(x, pre_W0, pre_b0, pre_W1, pre_b1, pre_W2, pre_b2, bufA);

    float* curbuf = bufA;
    float* nxtbuf = bufB;
    for (int l = 0; l < 3; l++) {
        k_msg<<<WMAX, 256>>>(curbuf, l);
        k_convgru<<<NN/16, 256>>>(curbuf, root_W + l*4096, conv_b + l*64,
                                  gru_Wih + l*64*192, gru_bih + l*192,
                                  gru_Whh + l*64*192, gru_bhh + l*192, nxtbuf);
        float* sw = curbuf; curbuf = nxtbuf; nxtbuf = sw;
    }

    k_s2s<<<BB, 256>>>(curbuf, s2s_Wih, s2s_Whh, s2s_bih, s2s_bhh,
                       post_W0, post_b0, post_W1, post_b1,
                       post_W2, post_b2, post_W3, post_b3, (float*)d_out);
}